// round 17
// baseline (speedup 1.0000x reference)
#include <cuda_runtime.h>
#include <cuda_fp16.h>
#include <cstdint>
#include <math.h>

#define BB 2048
#define SS 64
#define HH 256
#define NG 1024
#define AKW 512            // activation cols: [hi(256) | lo(256)]
#define KW_ENC 1024        // 2 * 512  (fp16 2-term split)
#define KW_AR  512         // 2 * 256
#define TM 64              // CTA tile M
#define TN 128             // CTA tile N
#define NCTA 256           // 8 x 32 grid, all co-resident (2/SM on 148 SMs)

// ---------------- static device scratch (no allocations) ----------------
__device__ __align__(128) __half g_hbuf[2][BB * AKW];           // ping-pong h (hi|lo)
__device__ __align__(128) float  g_c[BB * HH];                  // cell state fp32
__device__ __align__(128) __half g_Wb[NG * KW_ENC];             // [n][k] enc weights
__device__ __align__(128) __half g_Wsb[NG * KW_AR];             // [n][k] AR weights
__device__ __align__(128) __half g_xs[(size_t)SS * BB * AKW];   // x split per t
__device__ __align__(16)  float  g_bias[NG];
__device__ unsigned g_arrive;                                   // grid-barrier arrivals
__device__ unsigned g_release;                                  // grid-barrier generation

// ---------------- smem: 3-stage cp.async pipeline, stride-144B rows ----------------
#define ROWB    144
#define A_TILEB (TM * ROWB)           // 9216
#define B_TILEB (TN * ROWB)           // 18432
#define STAGEB  (A_TILEB + B_TILEB)   // 27648
#define STAGES  3
#define SM_TOT  (STAGES * STAGEB)     // 82944 B -> 2 CTAs/SM

__device__ __forceinline__ uint32_t smem_u32(const void* p) {
    uint32_t r;
    asm("{ .reg .u64 t; cvta.to.shared.u64 t, %1; cvt.u32.u64 %0, t; }" : "=r"(r) : "l"(p));
    return r;
}

#define CPASYNC16(saddr, gptr) \
    asm volatile("cp.async.cg.shared.global [%0], [%1], 16;" :: "r"(saddr), "l"(gptr))
#define CP_COMMIT() asm volatile("cp.async.commit_group;" ::: "memory")
#define CP_WAIT1()  asm volatile("cp.async.wait_group 1;" ::: "memory")
#define CP_WAIT0()  asm volatile("cp.async.wait_group 0;" ::: "memory")

#define LDSM4(r0, r1, r2, r3, addr)                                              \
    asm volatile("ldmatrix.sync.aligned.m8n8.x4.shared.b16 {%0,%1,%2,%3}, [%4];" \
                 : "=r"(r0), "=r"(r1), "=r"(r2), "=r"(r3) : "r"(addr))

#define MMA16816(d, a, b)                                                   \
    asm volatile("mma.sync.aligned.m16n8k16.row.col.f32.f16.f16.f32 "       \
                 "{%0,%1,%2,%3}, {%4,%5,%6,%7}, {%8,%9}, {%0,%1,%2,%3};"    \
                 : "+f"((d)[0]), "+f"((d)[1]), "+f"((d)[2]), "+f"((d)[3])   \
                 : "r"((a)[0]), "r"((a)[1]), "r"((a)[2]), "r"((a)[3]),      \
                   "r"((b)[0]), "r"((b)[1]))

// ---------------- init (also resets grid-barrier state each replay) ----------------
__global__ void init_k() {
    int idx = blockIdx.x * blockDim.x + threadIdx.x;
    const int stride = gridDim.x * blockDim.x;
    if (idx == 0) { g_arrive = 0u; g_release = 0u; }
    for (int i = idx; i < BB * AKW; i += stride) g_hbuf[0][i] = __float2half(0.0f);
    for (int i = idx; i < BB * HH; i += stride) g_c[i] = 0.0f;
}

// ---------------- weight prep: gate-interleave + K-concat (fp16) ----------------
// enc K segs (256 each): [Whh, Wih, Whh, Wih];  AR K segs: [Ws, Ws] (Ws = Wih+Whh)
__global__ void prep_w(const float* __restrict__ Wih, const float* __restrict__ Whh,
                       const float* __restrict__ bih, const float* __restrict__ bhh) {
    int idx = blockIdx.x * blockDim.x + threadIdx.x;
    const int stride = gridDim.x * blockDim.x;
    const int n1 = NG * KW_ENC;
    const int n2 = NG * KW_AR;
    const int total = n1 + n2 + NG;
    for (int i = idx; i < total; i += stride) {
        if (i < n1) {
            int n = i / KW_ENC, kk = i - n * KW_ENC;
            int g = n & 3, j = n >> 2, wrow = g * HH + j;
            int seg = kk >> 8, k = kk & 255;
            float v = (seg & 1) ? Wih[wrow * HH + k] : Whh[wrow * HH + k];
            g_Wb[i] = __float2half(v);
        } else if (i < n1 + n2) {
            int r = i - n1;
            int n = r / KW_AR, kk = r - n * KW_AR;
            int g = n & 3, j = n >> 2, wrow = g * HH + j;
            int k = kk & 255;
            g_Wsb[r] = __float2half(Wih[wrow * HH + k] + Whh[wrow * HH + k]);
        } else {
            int n = i - n1 - n2;
            int g = n & 3, j = n >> 2;
            g_bias[n] = bih[g * HH + j] + bhh[g * HH + j];
        }
    }
}

// ---------------- x split: [B,S,H] fp32 -> per-t [B, hi|lo] fp16 ----------------
__global__ void prep_x(const float* __restrict__ x0) {
    size_t idx = (size_t)blockIdx.x * blockDim.x + threadIdx.x;
    const size_t stride = (size_t)gridDim.x * blockDim.x;
    const size_t total = (size_t)SS * BB * HH;
    for (size_t i = idx; i < total; i += stride) {
        size_t tm = i / HH;
        int k = (int)(i - tm * HH);
        int m = (int)(tm % BB);
        int t = (int)(tm / BB);
        float v = x0[((size_t)m * SS + t) * HH + k];
        __half hi = __float2half(v);
        __half lo = __float2half(v - __half2float(hi));
        size_t base = ((size_t)t * BB + m) * AKW;
        g_xs[base + k] = hi;
        g_xs[base + 256 + k] = lo;
    }
}

// ---------------- chunk load pieces ----------------
__device__ __forceinline__ void issue_B(int kc, int stage, uint32_t sbase,
                                        int n0, const __half* __restrict__ W,
                                        int wstride, int tid) {
    const __half* bsrc = W + (size_t)kc * 64;
    const uint32_t Bb = sbase + stage * STAGEB + A_TILEB;
#pragma unroll
    for (int j = 0; j < 4; j++) {
        int idx = tid + j * 256;
        int row = idx >> 3, c8 = idx & 7;
        CPASYNC16(Bb + (uint32_t)(row * ROWB + c8 * 16),
                  (const void*)(bsrc + (size_t)(n0 + row) * wstride + c8 * 8));
    }
}

__device__ __forceinline__ void issue_A(int kc, int stage, uint32_t sbase,
                                        int m0, const __half* __restrict__ hin,
                                        const __half* __restrict__ xt, int enc,
                                        int tid) {
    const int seg = kc >> 2, off = (kc & 3) * 64;
    const __half* asrc; int acol;
    if (enc) {   // A segs: [h_hi, x_hi, h_lo, x_lo]
        switch (seg) {
            case 0:  asrc = hin; acol = off; break;
            case 1:  asrc = xt;  acol = off; break;
            case 2:  asrc = hin; acol = 256 + off; break;
            default: asrc = xt;  acol = 256 + off; break;
        }
    } else {     // A segs: [h_hi, h_lo]
        asrc = hin; acol = (seg == 1 ? 256 : 0) + off;
    }
    const uint32_t Ab = sbase + stage * STAGEB;
#pragma unroll
    for (int j = 0; j < 2; j++) {
        int idx = tid + j * 256;
        int row = idx >> 3, c8 = idx & 7;
        CPASYNC16(Ab + (uint32_t)(row * ROWB + c8 * 16),
                  (const void*)(asrc + (size_t)(m0 + row) * AKW + acol + c8 * 8));
    }
}

// ---------------- fragment loads for one k16 slice ----------------
__device__ __forceinline__ void load_frags(int ks, uint32_t Ab, uint32_t Bb,
                                           uint32_t a_off, uint32_t b_off,
                                           uint32_t af[2][4], uint32_t bf[4][2]) {
#pragma unroll
    for (int mt = 0; mt < 2; mt++)
        LDSM4(af[mt][0], af[mt][1], af[mt][2], af[mt][3],
              Ab + a_off + mt * (16 * ROWB) + ks * 32);
#pragma unroll
    for (int p = 0; p < 2; p++) {
        uint32_t r0, r1, r2, r3;
        LDSM4(r0, r1, r2, r3, Bb + b_off + p * (16 * ROWB) + ks * 32);
        bf[2 * p][0] = r0; bf[2 * p][1] = r1;
        bf[2 * p + 1][0] = r2; bf[2 * p + 1][1] = r3;
    }
}

__device__ __forceinline__ float sig_f(float x) {
    return __fdividef(1.0f, 1.0f + __expf(-x));
}
__device__ __forceinline__ float tanh_f(float x) {
    return 2.0f * sig_f(2.0f * x) - 1.0f;
}

// ---------------- persistent fused LSTM: all steps in one kernel ----------------
__global__ __launch_bounds__(256, 2)
void lstm_persist(int n_steps, float* __restrict__ out, int ostride) {
    extern __shared__ char smem[];
    const int tid = threadIdx.x;
    const int wid = tid >> 5, lane = tid & 31;
    const int warp_m = wid >> 2, warp_n = wid & 3;   // 2 x 4 warp grid, warp = 32x32
    const int n0 = blockIdx.x * TN, m0 = blockIdx.y * TM;
    const int NSTEP = SS + n_steps;

    const uint32_t sbase = smem_u32(smem);
    const uint32_t a_off = (uint32_t)((warp_m * 32 + (lane & 7) + ((lane >> 3) & 1) * 8) * ROWB
                                      + ((lane >> 4) & 1) * 16);
    const uint32_t b_off = (uint32_t)((warp_n * 32 + (lane & 7) + ((lane >> 4) & 1) * 8) * ROWB
                                      + ((lane >> 3) & 1) * 16);
    const int c = lane & 3, g = lane >> 2;

    // pre-issue B of step 0, chunks 0 and 1 (weights: known before any barrier)
    issue_B(0, 0, sbase, n0, g_Wb, KW_ENC, tid); CP_COMMIT();
    issue_B(1, 1, sbase, n0, g_Wb, KW_ENC, tid); CP_COMMIT();

    for (int step = 0; step < NSTEP; ++step) {
        const int enc = (step < SS);
        const __half* __restrict__ hin = g_hbuf[step & 1];
        __half* __restrict__ hout = g_hbuf[(step + 1) & 1];
        const __half* __restrict__ W = enc ? g_Wb : g_Wsb;
        const int wstride = enc ? KW_ENC : KW_AR;
        const int NCH = enc ? (KW_ENC / 64) : (KW_AR / 64);   // 16 or 8
        const __half* __restrict__ xt =
            enc ? (g_xs + (size_t)step * BB * AKW) : (const __half*)0;
        float* __restrict__ outp =
            (step == SS - 1) ? out
            : (step >= SS ? out + (size_t)(step - SS + 1) * HH : (float*)0);

        // A-parts of chunks 0, 1 (depend on h -> must be post-barrier)
        issue_A(0, 0, sbase, m0, hin, xt, enc, tid); CP_COMMIT();
        issue_A(1, 1, sbase, m0, hin, xt, enc, tid); CP_COMMIT();
        // groups: {B0, B1, A0, A1}; mainloop keeps wait_group 1 invariant:
        // iter 0: all-but-newest -> B0,B1,A0 done (chunk0 complete); newest A1 pending.

        float acc[2][4][4];
#pragma unroll
        for (int i = 0; i < 2; i++)
#pragma unroll
            for (int j = 0; j < 4; j++)
#pragma unroll
                for (int r = 0; r < 4; r++) acc[i][j][r] = 0.0f;

        int st_cur = 0, st_nxt = 2;
        for (int i = 0; i < NCH; i++) {
            CP_WAIT1();
            __syncthreads();

            const int nx = i + 2;
            if (nx < NCH) {
                issue_A(nx, st_nxt, sbase, m0, hin, xt, enc, tid);
                issue_B(nx, st_nxt, sbase, n0, W, wstride, tid);
            }
            CP_COMMIT();

            const uint32_t Ab = sbase + st_cur * STAGEB;
            const uint32_t Bb = Ab + A_TILEB;
            if (++st_cur == STAGES) st_cur = 0;
            if (++st_nxt == STAGES) st_nxt = 0;

            uint32_t af[2][2][4], bf[2][4][2];
            load_frags(0, Ab, Bb, a_off, b_off, af[0], bf[0]);
#pragma unroll
            for (int ks = 0; ks < 4; ks++) {
                const int cur = ks & 1;
                if (ks < 3)
                    load_frags(ks + 1, Ab, Bb, a_off, b_off, af[cur ^ 1], bf[cur ^ 1]);
#pragma unroll
                for (int mt = 0; mt < 2; mt++)
#pragma unroll
                    for (int nt = 0; nt < 4; nt++)
                        MMA16816(acc[mt][nt], af[cur][mt], bf[cur][nt]);
            }
        }

        CP_WAIT0();          // drain all groups (incl. empty commits) -> clean slate
        __syncthreads();     // all warps done with stages

        // ---------------- fused epilogue: quad gather -> gates -> (h, c) ----------
#pragma unroll
        for (int mt = 0; mt < 2; mt++)
#pragma unroll
            for (int nt = 0; nt < 4; nt++) {
                float q0 = acc[mt][nt][0], q1 = acc[mt][nt][1];
                float q2 = acc[mt][nt][2], q3 = acc[mt][nt][3];
                float p0 = __shfl_xor_sync(0xffffffffu, q0, 1);
                float p1 = __shfl_xor_sync(0xffffffffu, q1, 1);
                float p2 = __shfl_xor_sync(0xffffffffu, q2, 1);
                float p3 = __shfl_xor_sync(0xffffffffu, q3, 1);
                float gi, gf, gg, go;
                int row;
                if ((c & 1) == 0) { gi = q0; gf = q1; gg = p0; go = p1; row = g; }
                else              { gi = p2; gf = p3; gg = q2; go = q3; row = g + 8; }
                const int nq = n0 + warp_n * 32 + nt * 8 + (c >> 1) * 4;
                const int brow = m0 + warp_m * 32 + mt * 16 + row;
                const float4 bs = *(const float4*)&g_bias[nq];
                gi += bs.x; gf += bs.y; gg += bs.z; go += bs.w;
                const float iv = sig_f(gi);
                const float fv = sig_f(gf);
                const float gv = tanh_f(gg);
                const float ov = sig_f(go);
                const int j = nq >> 2;
                const int ci = brow * HH + j;
                const float cn = fv * g_c[ci] + iv * gv;
                const float hn = ov * tanh_f(cn);
                g_c[ci] = cn;
                __half hi = __float2half(hn);
                __half lo = __float2half(hn - __half2float(hi));
                hout[(size_t)brow * AKW + j] = hi;
                hout[(size_t)brow * AKW + 256 + j] = lo;
                if (outp) outp[(size_t)brow * ostride + j] = hn;
            }

        if (step + 1 < NSTEP) {
            // prefetch next step's B chunks 0,1 (weights independent of barrier)
            const __half* Wn = (step + 1 < SS) ? g_Wb : g_Wsb;
            const int wsn = (step + 1 < SS) ? KW_ENC : KW_AR;
            issue_B(0, 0, sbase, n0, Wn, wsn, tid); CP_COMMIT();
            issue_B(1, 1, sbase, n0, Wn, wsn, tid); CP_COMMIT();

            // ---------------- grid barrier (generation-based) ----------------
            __threadfence();     // make h/c stores visible gpu-wide (cumulative)
            __syncthreads();
            if (tid == 0) {
                unsigned old = atomicAdd(&g_arrive, 1u);
                if (old == (unsigned)(NCTA * (step + 1) - 1))
                    atomicExch(&g_release, (unsigned)(step + 1));
                while (*(volatile unsigned*)&g_release < (unsigned)(step + 1))
                    __nanosleep(64);
                __threadfence();
            }
            __syncthreads();
        }
    }
}

// ---------------- host launcher (graph-capturable, alloc-free) ----------------
extern "C" void kernel_launch(void* const* d_in, const int* in_sizes, int n_in,
                              void* d_out, int out_size) {
    const float* x0  = (const float*)d_in[0];
    const float* Wih = (const float*)d_in[1];
    const float* Whh = (const float*)d_in[2];
    const float* bih = (const float*)d_in[3];
    const float* bhh = (const float*)d_in[4];
    float* out = (float*)d_out;

    const int n_steps = out_size / (BB * HH) - 1;
    const int ostride = (n_steps + 1) * HH;

    cudaFuncSetAttribute(lstm_persist, cudaFuncAttributeMaxDynamicSharedMemorySize, SM_TOT);

    init_k<<<512, 256>>>();
    prep_w<<<2048, 256>>>(Wih, Whh, bih, bhh);
    prep_x<<<4096, 256>>>(x0);

    dim3 grid(8, BB / TM);   // 8 x 32 = 256 CTAs, all co-resident (2/SM)
    lstm_persist<<<grid, 256, SM_TOT>>>(n_steps, out, ostride);
}